// round 3
// baseline (speedup 1.0000x reference)
#include <cuda_runtime.h>
#include <cuda_bf16.h>

// ---------------------------------------------------------------------------
// 18-qubit statevector fidelity |<psi2|psi1>|^2, hardware-efficient ansatz.
// R3: 4 amps/thread (128K threads, 4096 warps ~ 6.9/SMSP) for latency hiding.
// Two passes per layer, each with one XOR-swizzled smem transpose:
//   passA: q0,q1(reg) q2-6(shfl) | transpose | q7,q8(reg) q9(shfl)
//   passB: q10-14(shfl)          | transpose | q15,16(reg) q17(shfl) + CZ
// ---------------------------------------------------------------------------

#define NQ 18
#define NL 6
#define NSTATE (1 << NQ)

__device__ float2 d_psi[2][NSTATE];
__device__ float2 d_mats[2][NL][NQ][4];
__device__ double d_acc[2];

__device__ __forceinline__ float2 cmul(float2 a, float2 b) {
    return make_float2(a.x * b.x - a.y * b.y, a.x * b.y + a.y * b.x);
}
__device__ __forceinline__ float2 cadd(float2 a, float2 b) {
    return make_float2(a.x + b.x, a.y + b.y);
}
__device__ __forceinline__ float2 rscale(float r, float2 v) {
    return make_float2(r * v.x, r * v.y);
}

__global__ void qk_prep(const float* __restrict__ x1, const float* __restrict__ x2,
                        const float* __restrict__ iscale, const float* __restrict__ var) {
    int t = threadIdx.x;
    if (t < 2) d_acc[t] = 0.0;
    if (t >= 2 * NL * NQ) return;
    int s = t / (NL * NQ);
    int r = t % (NL * NQ);
    int l = r / NQ;
    int q = r % NQ;
    const float* x = s ? x2 : x1;

    float a = iscale[l * NQ + q] * x[q];
    float b = var[l * 2 * NQ + q];
    float c = var[l * 2 * NQ + NQ + q];

    float sa, ca, sb, cb, sc, cc;
    sincosf(0.5f * a, &sa, &ca);
    sincosf(0.5f * b, &sb, &cb);
    sincosf(0.5f * c, &sc, &cc);

    float2 X00 = make_float2(ca, 0.f), X01 = make_float2(0.f, -sa);
    float2 X10 = make_float2(0.f, -sa), X11 = make_float2(ca, 0.f);
    float2 M100 = cadd(rscale(cb, X00), rscale(-sb, X10));
    float2 M101 = cadd(rscale(cb, X01), rscale(-sb, X11));
    float2 M110 = cadd(rscale(sb, X00), rscale(cb, X10));
    float2 M111 = cadd(rscale(sb, X01), rscale(cb, X11));
    float2 e0 = make_float2(cc, -sc);
    float2 e1 = make_float2(cc, sc);
    d_mats[s][l][q][0] = cmul(e0, M100);
    d_mats[s][l][q][1] = cmul(e0, M101);
    d_mats[s][l][q][2] = cmul(e1, M110);
    d_mats[s][l][q][3] = cmul(e1, M111);
}

__device__ __forceinline__ void gate_pair(float2& a, float2& b,
                                          float2 m00, float2 m01, float2 m10, float2 m11) {
    float2 na = cadd(cmul(m00, a), cmul(m01, b));
    float2 nb = cadd(cmul(m10, a), cmul(m11, b));
    a = na;
    b = nb;
}

// Hoisted-coefficient shfl gate: caller computes ca = hi?m11:m00, cb = hi?m10:m01
__device__ __forceinline__ float2 gate_shfl2(float2 v, int mask, float2 ca, float2 cb) {
    float2 p;
    p.x = __shfl_xor_sync(0xFFFFFFFFu, v.x, mask);
    p.y = __shfl_xor_sync(0xFFFFFFFFu, v.y, mask);
    return cadd(cmul(ca, v), cmul(cb, p));
}

// smem swizzle over 10-bit local index: conflict-free for both transpose patterns
__device__ __forceinline__ unsigned swz(unsigned l) {
    return l ^ ((l >> 4) & 3u) ^ ((l >> 8) & 2u);
}

// ---------------------------------------------------------------------------
// passA: qubits 0..9. 512 blocks x 256 threads, 4 amps/thread.
// Local index l (10 bits) == global amp bits 0-9; blk bits -> global 10-17.
// mapping1: l = k | lane<<2 | w<<7   (k: bits 0,1; lane: 2-6; w: 7-9)
// mapping2: l = (w&3) | (w>>2)<<6 | (lane&1)<<9 | ((lane>>1)&15)<<2 | k<<7
// ---------------------------------------------------------------------------
__global__ void __launch_bounds__(256) qk_passA(int layer, int init) {
    __shared__ float2 sm[1024];
    int tid = threadIdx.x;
    int lane = tid & 31;
    int w = tid >> 5;                               // 0..7
    int blk = blockIdx.x;                           // 0..511
    int s = blk >> 8;
    unsigned blkbase = ((unsigned)(blk & 255)) << 10;
    float2* psi = d_psi[s];
    const float2* M = &d_mats[s][layer][0][0];

    unsigned l1 = ((unsigned)lane << 2) | ((unsigned)w << 7);
    float2 v[4];

    if (init) {
#pragma unroll
        for (int k = 0; k < 4; k++) v[k] = make_float2(0.f, 0.f);
        if ((blkbase | l1) == 0) v[0] = make_float2(1.f, 0.f);
    } else {
        const float4* p4 = (const float4*)(psi + blkbase + l1);
        float4 a = p4[0], b = p4[1];
        v[0] = make_float2(a.x, a.y);
        v[1] = make_float2(a.z, a.w);
        v[2] = make_float2(b.x, b.y);
        v[3] = make_float2(b.z, b.w);
    }

    // reg gates q0 (stride 1), q1 (stride 2)
    {
        float2 m00 = M[0], m01 = M[1], m10 = M[2], m11 = M[3];
        gate_pair(v[0], v[1], m00, m01, m10, m11);
        gate_pair(v[2], v[3], m00, m01, m10, m11);
    }
    {
        float2 m00 = M[4], m01 = M[5], m10 = M[6], m11 = M[7];
        gate_pair(v[0], v[2], m00, m01, m10, m11);
        gate_pair(v[1], v[3], m00, m01, m10, m11);
    }
    // shfl gates q2..q6 (lane bits 0..4)
#pragma unroll
    for (int q = 2; q < 7; q++) {
        int mask = 1 << (q - 2);
        bool hi = (lane & mask) != 0;
        float2 ca = hi ? M[q * 4 + 3] : M[q * 4 + 0];
        float2 cb = hi ? M[q * 4 + 2] : M[q * 4 + 1];
#pragma unroll
        for (int k = 0; k < 4; k++) v[k] = gate_shfl2(v[k], mask, ca, cb);
    }

    // transpose
#pragma unroll
    for (int k = 0; k < 4; k++) sm[swz(l1 | k)] = v[k];
    __syncthreads();

    unsigned base2 = (unsigned)(w & 3) | ((unsigned)(w >> 2) << 6)
                   | ((unsigned)(lane & 1) << 9) | ((unsigned)((lane >> 1) & 15) << 2);
#pragma unroll
    for (int k = 0; k < 4; k++) v[k] = sm[swz(base2 | ((unsigned)k << 7))];

    // reg gates q7 (k stride 1), q8 (k stride 2)
    {
        float2 m00 = M[28], m01 = M[29], m10 = M[30], m11 = M[31];
        gate_pair(v[0], v[1], m00, m01, m10, m11);
        gate_pair(v[2], v[3], m00, m01, m10, m11);
    }
    {
        float2 m00 = M[32], m01 = M[33], m10 = M[34], m11 = M[35];
        gate_pair(v[0], v[2], m00, m01, m10, m11);
        gate_pair(v[1], v[3], m00, m01, m10, m11);
    }
    // shfl gate q9 (lane bit 0)
    {
        bool hi = (lane & 1) != 0;
        float2 ca = hi ? M[39] : M[36];
        float2 cb = hi ? M[38] : M[37];
#pragma unroll
        for (int k = 0; k < 4; k++) v[k] = gate_shfl2(v[k], 1, ca, cb);
    }

#pragma unroll
    for (int k = 0; k < 4; k++)
        psi[blkbase + base2 + ((unsigned)k << 7)] = v[k];
}

// ---------------------------------------------------------------------------
// passB: qubits 10..17 + CZ sign. Block owns global bits {0,1,10..17};
// global bits 2-9 come from blockIdx. Local l: bits 0,1 -> global 0,1;
// local bits 2-9 -> global 10-17.  global(l) = (l&3) | rest<<2 | (l>>2)<<10
// mapping1: l = k | lane<<2 | w<<7   -> shfl gates q10-14 (lane bits)
// mapping2: same remap as passA      -> reg q15,q16 (k'), shfl q17 (lane' bit0)
// ---------------------------------------------------------------------------
__global__ void __launch_bounds__(256) qk_passB(int layer) {
    __shared__ float2 sm[1024];
    int tid = threadIdx.x;
    int lane = tid & 31;
    int w = tid >> 5;
    int blk = blockIdx.x;
    int s = blk >> 8;
    unsigned rest = (unsigned)(blk & 255);          // global bits 2-9
    float2* psi = d_psi[s];
    const float2* M = &d_mats[s][layer][0][0];

    unsigned l1 = ((unsigned)lane << 2) | ((unsigned)w << 7);
    unsigned g1 = (l1 & 3u) | (rest << 2) | ((l1 >> 2) << 10);

    float2 v[4];
    {
        const float4* p4 = (const float4*)(psi + g1);
        float4 a = p4[0], b = p4[1];
        v[0] = make_float2(a.x, a.y);
        v[1] = make_float2(a.z, a.w);
        v[2] = make_float2(b.x, b.y);
        v[3] = make_float2(b.z, b.w);
    }

    // shfl gates q10..q14 (lane bits 0..4)
#pragma unroll
    for (int q = 10; q < 15; q++) {
        int mask = 1 << (q - 10);
        bool hi = (lane & mask) != 0;
        float2 ca = hi ? M[q * 4 + 3] : M[q * 4 + 0];
        float2 cb = hi ? M[q * 4 + 2] : M[q * 4 + 1];
#pragma unroll
        for (int k = 0; k < 4; k++) v[k] = gate_shfl2(v[k], mask, ca, cb);
    }

#pragma unroll
    for (int k = 0; k < 4; k++) sm[swz(l1 | k)] = v[k];
    __syncthreads();

    unsigned base2 = (unsigned)(w & 3) | ((unsigned)(w >> 2) << 6)
                   | ((unsigned)(lane & 1) << 9) | ((unsigned)((lane >> 1) & 15) << 2);
#pragma unroll
    for (int k = 0; k < 4; k++) v[k] = sm[swz(base2 | ((unsigned)k << 7))];

    // reg gates q15 (local bit7, stride 1 in k), q16 (local bit8, stride 2)
    {
        float2 m00 = M[60], m01 = M[61], m10 = M[62], m11 = M[63];
        gate_pair(v[0], v[1], m00, m01, m10, m11);
        gate_pair(v[2], v[3], m00, m01, m10, m11);
    }
    {
        float2 m00 = M[64], m01 = M[65], m10 = M[66], m11 = M[67];
        gate_pair(v[0], v[2], m00, m01, m10, m11);
        gate_pair(v[1], v[3], m00, m01, m10, m11);
    }
    // shfl gate q17 (local bit9 = lane' bit0)
    {
        bool hi = (lane & 1) != 0;
        float2 ca = hi ? M[71] : M[68];
        float2 cb = hi ? M[70] : M[69];
#pragma unroll
        for (int k = 0; k < 4; k++) v[k] = gate_shfl2(v[k], 1, ca, cb);
    }

    // CZ chain sign + store
#pragma unroll
    for (int k = 0; k < 4; k++) {
        unsigned l2 = base2 | ((unsigned)k << 7);
        unsigned g = (l2 & 3u) | (rest << 2) | ((l2 >> 2) << 10);
        unsigned tm = g & (g >> 1) & 0x1FFFFu;
        if (__popc(tm) & 1) {
            v[k].x = -v[k].x;
            v[k].y = -v[k].y;
        }
        psi[g] = v[k];
    }
}

__global__ void qk_reduce() {
    int t = blockIdx.x * blockDim.x + threadIdx.x;
    int nthreads = gridDim.x * blockDim.x;
    double re = 0.0, im = 0.0;
    for (int i = t; i < NSTATE; i += nthreads) {
        float2 a = d_psi[0][i];
        float2 b = d_psi[1][i];
        re += (double)b.x * a.x + (double)b.y * a.y;
        im += (double)b.x * a.y - (double)b.y * a.x;
    }
#pragma unroll
    for (int o = 16; o > 0; o >>= 1) {
        re += __shfl_down_sync(0xFFFFFFFFu, re, o);
        im += __shfl_down_sync(0xFFFFFFFFu, im, o);
    }
    if ((threadIdx.x & 31) == 0) {
        atomicAdd(&d_acc[0], re);
        atomicAdd(&d_acc[1], im);
    }
}

__global__ void qk_final(float* out) {
    double re = d_acc[0], im = d_acc[1];
    out[0] = (float)(re * re + im * im);
}

extern "C" void kernel_launch(void* const* d_in, const int* in_sizes, int n_in,
                              void* d_out, int out_size) {
    const float* x1 = (const float*)d_in[0];
    const float* x2 = (const float*)d_in[1];
    const float* iscale = (const float*)d_in[2];
    const float* var = (const float*)d_in[3];

    qk_prep<<<1, 256>>>(x1, x2, iscale, var);
    for (int l = 0; l < NL; l++) {
        qk_passA<<<512, 256>>>(l, l == 0 ? 1 : 0);
        qk_passB<<<512, 256>>>(l);
    }
    qk_reduce<<<148, 256>>>();
    qk_final<<<1, 1>>>((float*)d_out);
}